// round 16
// baseline (speedup 1.0000x reference)
#include <cuda_runtime.h>
#include <cuda_fp16.h>
#include <mma.h>
#include <math.h>
#include <stdint.h>

using namespace nvcuda;

// Problem constants
#define Bb 4
#define Ss 1024
#define Dd 512
#define Ee 64
#define Hh 8
#define BS (Bb*Ss)      // 4096
#define DH (Dd*Hh)      // 4096

// ---------------- Scratch (device globals; no allocation allowed) ----------------
__device__ __half g_xh[BS*Dd];             // fp16 copy of x
__device__ __half g_Wqkvh[Hh*Dd*640];      // packed fp16 [H][512][640] = Wq|Wk|Wv
__device__ __half g_Woh[DH*Dd];            // fp16 Wo (original layout)
__device__ __half g_W1h[Dd*Dd];
__device__ __half g_W2h[Dd*Dd];
__device__ __half g_QKV[Hh*BS*640];        // [H][B*S][640]: Q|K|V per row (fp16)
__device__ __half g_P[(long)Hh*Bb*Ss*Ss]; // [z][1024][1024] unnormalized probs (64MB fp16)
__device__ float  g_lpart[Hh*Bb*8*Ss];     // [z][xtile(8)][row] partial row sums
__device__ __half g_O[Hh*BS*Dd];           // [H][B*S][512] attention out (fp16, pre-Wo)
__device__ float  g_attn[BS*Dd];
__device__ float  g_x1[BS*Dd];
__device__ __half g_x1h[BS*Dd];
__device__ __half g_h1[BS*Dd];
__device__ float  g_f[BS*Dd];

// ---------------- helpers ----------------
__device__ __forceinline__ uint32_t s2u(const void* p) {
    uint32_t a;
    asm("{ .reg .u64 t; cvta.to.shared.u64 t, %1; cvt.u32.u64 %0, t; }" : "=r"(a) : "l"(p));
    return a;
}
__device__ __forceinline__ void cp16(uint32_t dst, const void* src) {
    asm volatile("cp.async.cg.shared.global [%0], [%1], 16;" :: "r"(dst), "l"(src) : "memory");
}
union H2U2 { __half2 h[2]; uint2 u; };

// ---------------- FP16 WMMA GEMM, fp16 gmem operands, cp.async pipeline ----------------
// (R13-proven engine: BK=32, 2-stage, two __syncthreads per iteration.)
// C = alpha * A @ op(B) [+bias / +ELU / exp+rowsum], batched over blockIdx.z.
// TRANSB: B is [N,K] row-major (fp16). Else B is [K,N] row-major.
// KPERM (Wo GEMM): k = h*512 + d;
//   A element (m,k) = O[h, m, d] ; B element (k,n) = Wo[d*8 + h, n]
// ACT: 0 none, 1 +bias, 2 +bias+ELU, 3 exp(alpha*v) + row partial sums -> lpart
// DIVROW: divide rows by sum of 8 lpart partials.  OUTH: C is fp16.
// Block 128x128, BK=32; 8 warps of 64x32 (4x2 m16n16k16).
// STATIC SMEM (halves), per stage 10240 (20480 B):
//   As: [128][40] ld=40 (5120 halves, byte off 0)
//   Bs: byte off 10240; TRANSB -> [128][40] ld=40 ; else [32][136] ld=136
#define STAGE_H 10240
#define STAGE_B (STAGE_H*2)
#define B_OFF_B (5120*2)

template<bool TRANSB, int ACT, bool KPERM, bool DIVROW, bool OUTH>
__global__ __launch_bounds__(256, 2)
void tgemm(const __half* __restrict__ A, const __half* __restrict__ B,
           void* __restrict__ Cv, const float* __restrict__ bias,
           float* __restrict__ lpart,
           int M, int N, int K, int lda, int ldb, int ldc,
           float alpha, long sA, long sB, long sC)
{
    const int BK = 32;
    __shared__ __align__(128) __half pool[2 * STAGE_H];
    __shared__ float sm_l[4][128];

    const int z = blockIdx.z;
    const __half* Ab = A + (long)z * sA;
    const __half* Bp = B + (long)z * sB;

    const int tid = threadIdx.x;
    const int wid = tid >> 5, lane = tid & 31;
    const int wm = (wid & 1) * 64, wn = (wid >> 1) * 32;
    const int row0 = blockIdx.y * 128, col0 = blockIdx.x * 128;
    const uint32_t base = s2u(pool);

    wmma::fragment<wmma::accumulator, 16, 16, 16, float> acc[4][2];
    #pragma unroll
    for (int i = 0; i < 4; i++)
        #pragma unroll
        for (int j = 0; j < 2; j++)
            wmma::fill_fragment(acc[i][j], 0.0f);

    auto load_stage = [&](int kt) {
        const int k0 = kt * BK;
        const uint32_t sb = base + (uint32_t)(kt & 1) * STAGE_B;
        // A: 128 rows x 32 halves, chunks of 8 halves
        #pragma unroll
        for (int i = 0; i < 2; i++) {
            int e = tid + i * 256;
            int r = e >> 2, c = e & 3;
            int k = k0 + 8 * c;
            const __half* src;
            if (KPERM) src = A + (long)(k >> 9) * ((long)BS * 512) + (long)(row0 + r) * 512 + (k & 511);
            else       src = Ab + (long)(row0 + r) * lda + k;
            cp16(sb + (uint32_t)(r * 40 + 8 * c) * 2, src);
        }
        if (TRANSB) {
            #pragma unroll
            for (int i = 0; i < 2; i++) {
                int e = tid + i * 256;
                int r = e >> 2, c = e & 3;
                const __half* src = Bp + (long)(col0 + r) * ldb + k0 + 8 * c;
                cp16(sb + (uint32_t)B_OFF_B + (uint32_t)(r * 40 + 8 * c) * 2, src);
            }
        } else {
            #pragma unroll
            for (int i = 0; i < 2; i++) {
                int e = tid + i * 256;
                int kk = e >> 4, c = e & 15;
                int k = k0 + kk, n = col0 + 8 * c;
                const __half* src;
                if (KPERM) src = B + ((long)(k & 511) * 8 + (k >> 9)) * 512 + n;
                else       src = Bp + (long)k * ldb + n;
                cp16(sb + (uint32_t)B_OFF_B + (uint32_t)(kk * 136 + 8 * c) * 2, src);
            }
        }
        asm volatile("cp.async.commit_group;" ::: "memory");
    };

    auto comp = [&](int st) {
        const __half* As_ = pool + st * STAGE_H;
        const __half* Bs_ = pool + st * STAGE_H + 5120;
        #pragma unroll
        for (int kb = 0; kb < BK; kb += 16) {
            wmma::fragment<wmma::matrix_a, 16, 16, 16, __half, wmma::row_major> af[4];
            #pragma unroll
            for (int mb = 0; mb < 4; mb++)
                wmma::load_matrix_sync(af[mb], As_ + (wm + mb * 16) * 40 + kb, 40);
            #pragma unroll
            for (int nb = 0; nb < 2; nb++) {
                if (TRANSB) {
                    wmma::fragment<wmma::matrix_b, 16, 16, 16, __half, wmma::col_major> bf;
                    wmma::load_matrix_sync(bf, Bs_ + (wn + nb * 16) * 40 + kb, 40);
                    #pragma unroll
                    for (int mb = 0; mb < 4; mb++)
                        wmma::mma_sync(acc[mb][nb], af[mb], bf, acc[mb][nb]);
                } else {
                    wmma::fragment<wmma::matrix_b, 16, 16, 16, __half, wmma::row_major> bf;
                    wmma::load_matrix_sync(bf, Bs_ + kb * 136 + wn + nb * 16, 136);
                    #pragma unroll
                    for (int mb = 0; mb < 4; mb++)
                        wmma::mma_sync(acc[mb][nb], af[mb], bf, acc[mb][nb]);
                }
            }
        }
    };

    const int nk = K / BK;
    load_stage(0);
    for (int kt = 0; kt < nk; kt++) {
        if (kt + 1 < nk) {
            load_stage(kt + 1);
            asm volatile("cp.async.wait_group 1;" ::: "memory");
        } else {
            asm volatile("cp.async.wait_group 0;" ::: "memory");
        }
        __syncthreads();
        comp(kt & 1);
        __syncthreads();
    }

    // Epilogue: stage 16x32 warp slabs through smem for explicit (row,col) math.
    float* scratch = (float*)pool + wid * 640;   // [16][40]
    const int r = lane >> 1, chalf = (lane & 1) * 16;

    #pragma unroll
    for (int mb = 0; mb < 4; mb++) {
        wmma::store_matrix_sync(scratch,      acc[mb][0], 40, wmma::mem_row_major);
        wmma::store_matrix_sync(scratch + 16, acc[mb][1], 40, wmma::mem_row_major);
        __syncwarp();

        const int m = row0 + wm + mb * 16 + r;
        float inv = 1.0f;
        if (DIVROW) {
            float ls = 0.f;
            #pragma unroll
            for (int j = 0; j < 8; j++) ls += lpart[(long)z * 8192 + j * 1024 + m];
            inv = 1.0f / ls;
        }
        float rs = 0.f;
        #pragma unroll
        for (int it = 0; it < 4; it++) {
            int c = chalf + it * 4;
            float4 v = *(float4*)(scratch + r * 40 + c);
            int n = col0 + wn + c;
            v.x *= alpha; v.y *= alpha; v.z *= alpha; v.w *= alpha;
            if (ACT == 1 || ACT == 2) {
                v.x += bias[n];     v.y += bias[n + 1];
                v.z += bias[n + 2]; v.w += bias[n + 3];
            }
            if (ACT == 2) {
                v.x = v.x > 0.f ? v.x : expm1f(v.x);
                v.y = v.y > 0.f ? v.y : expm1f(v.y);
                v.z = v.z > 0.f ? v.z : expm1f(v.z);
                v.w = v.w > 0.f ? v.w : expm1f(v.w);
            }
            if (ACT == 3) {
                v.x = __expf(v.x); v.y = __expf(v.y);
                v.z = __expf(v.z); v.w = __expf(v.w);
                rs += v.x + v.y + v.z + v.w;
            }
            if (DIVROW) { v.x *= inv; v.y *= inv; v.z *= inv; v.w *= inv; }
            if (OUTH) {
                __half* Ch = (__half*)Cv + (long)z * sC;
                H2U2 pk;
                pk.h[0] = __floats2half2_rn(v.x, v.y);
                pk.h[1] = __floats2half2_rn(v.z, v.w);
                *(uint2*)&Ch[(long)m * ldc + n] = pk.u;
            } else {
                float* Cf = (float*)Cv + (long)z * sC;
                *(float4*)&Cf[(long)m * ldc + n] = v;
            }
        }
        if (ACT == 3) {
            rs += __shfl_xor_sync(0xffffffffu, rs, 1);
            if ((lane & 1) == 0) sm_l[wid >> 1][wm + mb * 16 + r] = rs;
        }
        __syncwarp();
    }

    if (ACT == 3) {
        __syncthreads();
        if (tid < 128) {
            float s = sm_l[0][tid] + sm_l[1][tid] + sm_l[2][tid] + sm_l[3][tid];
            lpart[(long)z * 8192 + blockIdx.x * 1024 + row0 + tid] = s;
        }
    }
}

// ---------------- fp32 -> fp16, 4 regions in one launch ----------------
__global__ __launch_bounds__(256)
void cvt4(const float* __restrict__ s0, __half* __restrict__ d0, int n0,
          const float* __restrict__ s1, __half* __restrict__ d1, int n1,
          const float* __restrict__ s2, __half* __restrict__ d2, int n2,
          const float* __restrict__ s3, __half* __restrict__ d3, int n3)
{
    int i = blockIdx.x * 256 + threadIdx.x;
    const float* s; __half* d;
    if (i < n0) { s = s0; d = d0; }
    else if ((i -= n0) < n1) { s = s1; d = d1; }
    else if ((i -= n1) < n2) { s = s2; d = d2; }
    else if ((i -= n2) < n3) { s = s3; d = d3; }
    else return;
    float4 v = ((const float4*)s)[i];
    H2U2 pk;
    pk.h[0] = __floats2half2_rn(v.x, v.y);
    pk.h[1] = __floats2half2_rn(v.z, v.w);
    ((uint2*)d)[i] = pk.u;
}

// ---------------- Pack Wq|Wk|Wv -> fp16 [H][512][640] ----------------
__global__ __launch_bounds__(256)
void pack_wqkv(const float* __restrict__ Wq, const float* __restrict__ Wk,
               const float* __restrict__ Wv, __half* __restrict__ W)
{
    int idx = blockIdx.x * 256 + threadIdx.x;   // over H*512*640
    int col = idx % 640;
    int hd  = idx / 640;                        // h*512 + d
    float v;
    if (col < 64)       v = Wq[(long)hd * 64 + col];
    else if (col < 128) v = Wk[(long)hd * 64 + (col - 64)];
    else                v = Wv[(long)hd * 512 + (col - 128)];
    W[idx] = __float2half(v);
}

// ---------------- Fused residual + LayerNorm, 512 cols (+optional fp16 copy) ----------------
__global__ __launch_bounds__(256)
void residual_ln(const float* __restrict__ X, const float* __restrict__ Y,
                 const float* __restrict__ g, const float* __restrict__ be,
                 float* __restrict__ out, __half* __restrict__ outh)
{
    const int NC = Dd;
    long row = blockIdx.x;
    const float* x = X + row * NC;
    const float* y = Y + row * NC;
    float* o = out + row * NC;
    int tid = threadIdx.x;
    __shared__ float red[256];

    float v0 = x[tid] + y[tid];
    float v1 = x[tid + 256] + y[tid + 256];

    red[tid] = v0 + v1; __syncthreads();
    for (int s = 128; s > 0; s >>= 1) {
        if (tid < s) red[tid] += red[tid + s];
        __syncthreads();
    }
    float mu = red[0] * (1.f / NC); __syncthreads();

    float d0 = v0 - mu, d1 = v1 - mu;
    red[tid] = d0 * d0 + d1 * d1; __syncthreads();
    for (int s = 128; s > 0; s >>= 1) {
        if (tid < s) red[tid] += red[tid + s];
        __syncthreads();
    }
    float rstd = rsqrtf(red[0] * (1.f / NC) + 1e-5f);

    float r0 = d0 * rstd * g[tid]       + be[tid];
    float r1 = d1 * rstd * g[tid + 256] + be[tid + 256];
    o[tid] = r0;
    o[tid + 256] = r1;
    if (outh) {
        outh[row * NC + tid]       = __float2half(r0);
        outh[row * NC + tid + 256] = __float2half(r1);
    }
}

// ---------------- Launch ----------------
extern "C" void kernel_launch(void* const* d_in, const int* in_sizes, int n_in,
                              void* d_out, int out_size)
{
    const float* x  = (const float*)d_in[0];
    const float* Wq = (const float*)d_in[1];
    const float* Wk = (const float*)d_in[2];
    const float* Wv = (const float*)d_in[3];
    const float* Wo = (const float*)d_in[4];
    const float* W1 = (const float*)d_in[5];
    const float* b1 = (const float*)d_in[6];
    const float* W2 = (const float*)d_in[7];
    const float* b2 = (const float*)d_in[8];
    const float* g1 = (const float*)d_in[9];
    const float* be1= (const float*)d_in[10];
    const float* g2 = (const float*)d_in[11];
    const float* be2= (const float*)d_in[12];
    float* out = (float*)d_out;

    __half *xh, *Wqkvh, *Woh, *W1h, *W2h, *QKV, *P, *O, *x1h, *h1;
    float *lp, *attn, *x1, *f;
    cudaGetSymbolAddress((void**)&xh,    g_xh);
    cudaGetSymbolAddress((void**)&Wqkvh, g_Wqkvh);
    cudaGetSymbolAddress((void**)&Woh,   g_Woh);
    cudaGetSymbolAddress((void**)&W1h,   g_W1h);
    cudaGetSymbolAddress((void**)&W2h,   g_W2h);
    cudaGetSymbolAddress((void**)&QKV,   g_QKV);
    cudaGetSymbolAddress((void**)&P,     g_P);
    cudaGetSymbolAddress((void**)&lp,    g_lpart);
    cudaGetSymbolAddress((void**)&O,     g_O);
    cudaGetSymbolAddress((void**)&attn,  g_attn);
    cudaGetSymbolAddress((void**)&x1,    g_x1);
    cudaGetSymbolAddress((void**)&x1h,   g_x1h);
    cudaGetSymbolAddress((void**)&h1,    g_h1);
    cudaGetSymbolAddress((void**)&f,     g_f);

    // 0. conversions / packs (2 launches)
    const int n_x = BS*Dd/4, n_wo = DH*Dd/4, n_w = Dd*Dd/4;
    cvt4<<<(n_x + n_wo + 2*n_w + 255)/256, 256>>>(
        x, xh, n_x, Wo, Woh, n_wo, W1, W1h, n_w, W2, W2h, n_w);
    pack_wqkv<<<(Hh*Dd*640)/256, 256>>>(Wq, Wk, Wv, Wqkvh);

    // 1. QKV[h] = x @ Wqkv[h]   [4096,512]x[512,640] per head, fp16 out
    tgemm<false,0,false,false,true><<<dim3(5, 32, Hh), 256>>>(
        xh, Wqkvh, QKV, nullptr, nullptr, BS, 640, Dd, Dd, 640, 640, 1.f,
        0L, (long)Dd*640, (long)BS*640);
    // 2. P = exp(Q @ K^T / 8), row partials -> lpart   per z=(h,b), fp16 out
    tgemm<true,3,false,false,true><<<dim3(8, 8, Hh*Bb), 256>>>(
        QKV, QKV + 64, P, nullptr, lp, Ss, Ss, Ee, 640, 640, Ss, 0.125f,
        (long)Ss*640, (long)Ss*640, (long)Ss*Ss);
    // 3. O = (P @ V) / rowsum   per z: [1024,1024]x[1024,512], fp16 out
    tgemm<false,0,false,true,true><<<dim3(4, 8, Hh*Bb), 256>>>(
        P, QKV + 128, O, nullptr, lp, Ss, Dd, Ss, Ss, 640, Dd, 1.f,
        (long)Ss*Ss, (long)Ss*640, (long)Ss*Dd);
    // 4. attn = a @ Wo with k=(h,d) permutation folded into the loads, fp32 out
    tgemm<false,0,true,false,false><<<dim3(4, 32, 1), 256>>>(
        O, Woh, attn, nullptr, nullptr, BS, Dd, DH, Dd, Dd, Dd, 1.f, 0L, 0L, 0L);
    // 5. x1 = LN(x + attn)  (fp32 + fp16 copy)
    residual_ln<<<BS, 256>>>(x, attn, g1, be1, x1, x1h);
    // 6. h1 = ELU(x1 @ W1 + b1), fp16 out
    tgemm<false,2,false,false,true><<<dim3(4, 32, 1), 256>>>(
        x1h, W1h, h1, b1, nullptr, BS, Dd, Dd, Dd, Dd, Dd, 1.f, 0L, 0L, 0L);
    // 7. f = h1 @ W2 + b2, fp32 out
    tgemm<false,1,false,false,false><<<dim3(4, 32, 1), 256>>>(
        h1, W2h, f, b2, nullptr, BS, Dd, Dd, Dd, Dd, Dd, 1.f, 0L, 0L, 0L);
    // 8. out = LN(x1 + f)
    residual_ln<<<BS, 256>>>(x1, f, g2, be2, out, nullptr);
}

// round 17
// speedup vs baseline: 1.0092x; 1.0092x over previous
#include <cuda_runtime.h>
#include <cuda_fp16.h>
#include <mma.h>
#include <math.h>
#include <stdint.h>

using namespace nvcuda;

// Problem constants
#define Bb 4
#define Ss 1024
#define Dd 512
#define Ee 64
#define Hh 8
#define BS (Bb*Ss)      // 4096
#define DH (Dd*Hh)      // 4096

// ---------------- Scratch (device globals; no allocation allowed) ----------------
__device__ __half g_xh[BS*Dd];             // fp16 copy of x
__device__ __half g_Wqkvh[Hh*Dd*640];      // packed fp16 [H][512][640] = Wq|Wk|Wv
__device__ __half g_Woh[DH*Dd];            // fp16 Wo (original layout)
__device__ __half g_W1h[Dd*Dd];
__device__ __half g_W2h[Dd*Dd];
__device__ __half g_QKV[Hh*BS*640];        // [H][B*S][640]: Q|K|V per row (fp16)
__device__ __half g_P[(long)Hh*Bb*Ss*Ss]; // [z][1024][1024] unnormalized probs (64MB fp16)
__device__ float  g_lpart[Hh*Bb*8*Ss];     // [z][xtile(8)][row] partial row sums
__device__ __half g_O[Hh*BS*Dd];           // [H][B*S][512] attention out (fp16, pre-Wo)
__device__ float  g_attn[BS*Dd];
__device__ float  g_x1[BS*Dd];
__device__ __half g_x1h[BS*Dd];
__device__ __half g_h1[BS*Dd];
__device__ float  g_f[BS*Dd];

// ---------------- helpers ----------------
__device__ __forceinline__ uint32_t s2u(const void* p) {
    uint32_t a;
    asm("{ .reg .u64 t; cvta.to.shared.u64 t, %1; cvt.u32.u64 %0, t; }" : "=r"(a) : "l"(p));
    return a;
}
__device__ __forceinline__ void cp16(uint32_t dst, const void* src) {
    asm volatile("cp.async.cg.shared.global [%0], [%1], 16;" :: "r"(dst), "l"(src) : "memory");
}
union H2U2 { __half2 h[2]; uint2 u; };

// ---------------- FP16 WMMA GEMM, fp16 gmem operands, cp.async pipeline ----------------
// (R13-proven engine: BK=32, 2-stage, two __syncthreads per iteration.)
// C = alpha * A @ op(B) [+bias / +ELU / exp+rowsum], batched over blockIdx.z.
// TRANSB: B is [N,K] row-major (fp16). Else B is [K,N] row-major.
// KPERM (Wo GEMM): k = h*512 + d;
//   A element (m,k) = O[h, m, d] ; B element (k,n) = Wo[d*8 + h, n]
// ACT: 0 none, 1 +bias, 2 +bias+ELU, 3 exp(alpha*v) + row partial sums -> lpart
// DIVROW: divide rows by sum of 8 lpart partials.  OUTH: C is fp16.
// Block 128x128, BK=32; 8 warps of 64x32 (4x2 m16n16k16).
// STATIC SMEM (halves), per stage 10240 (20480 B):
//   As: [128][40] ld=40 (5120 halves, byte off 0)
//   Bs: byte off 10240; TRANSB -> [128][40] ld=40 ; else [32][136] ld=136
#define STAGE_H 10240
#define STAGE_B (STAGE_H*2)
#define B_OFF_B (5120*2)

template<bool TRANSB, int ACT, bool KPERM, bool DIVROW, bool OUTH>
__global__ __launch_bounds__(256, 2)
void tgemm(const __half* __restrict__ A, const __half* __restrict__ B,
           void* __restrict__ Cv, const float* __restrict__ bias,
           float* __restrict__ lpart,
           int M, int N, int K, int lda, int ldb, int ldc,
           float alpha, long sA, long sB, long sC)
{
    const int BK = 32;
    __shared__ __align__(128) __half pool[2 * STAGE_H];
    __shared__ float sm_l[4][128];

    const int z = blockIdx.z;
    const __half* Ab = A + (long)z * sA;
    const __half* Bp = B + (long)z * sB;

    const int tid = threadIdx.x;
    const int wid = tid >> 5, lane = tid & 31;
    const int wm = (wid & 1) * 64, wn = (wid >> 1) * 32;
    const int row0 = blockIdx.y * 128, col0 = blockIdx.x * 128;
    const uint32_t base = s2u(pool);

    wmma::fragment<wmma::accumulator, 16, 16, 16, float> acc[4][2];
    #pragma unroll
    for (int i = 0; i < 4; i++)
        #pragma unroll
        for (int j = 0; j < 2; j++)
            wmma::fill_fragment(acc[i][j], 0.0f);

    auto load_stage = [&](int kt) {
        const int k0 = kt * BK;
        const uint32_t sb = base + (uint32_t)(kt & 1) * STAGE_B;
        // A: 128 rows x 32 halves, chunks of 8 halves
        #pragma unroll
        for (int i = 0; i < 2; i++) {
            int e = tid + i * 256;
            int r = e >> 2, c = e & 3;
            int k = k0 + 8 * c;
            const __half* src;
            if (KPERM) src = A + (long)(k >> 9) * ((long)BS * 512) + (long)(row0 + r) * 512 + (k & 511);
            else       src = Ab + (long)(row0 + r) * lda + k;
            cp16(sb + (uint32_t)(r * 40 + 8 * c) * 2, src);
        }
        if (TRANSB) {
            #pragma unroll
            for (int i = 0; i < 2; i++) {
                int e = tid + i * 256;
                int r = e >> 2, c = e & 3;
                const __half* src = Bp + (long)(col0 + r) * ldb + k0 + 8 * c;
                cp16(sb + (uint32_t)B_OFF_B + (uint32_t)(r * 40 + 8 * c) * 2, src);
            }
        } else {
            #pragma unroll
            for (int i = 0; i < 2; i++) {
                int e = tid + i * 256;
                int kk = e >> 4, c = e & 15;
                int k = k0 + kk, n = col0 + 8 * c;
                const __half* src;
                if (KPERM) src = B + ((long)(k & 511) * 8 + (k >> 9)) * 512 + n;
                else       src = Bp + (long)k * ldb + n;
                cp16(sb + (uint32_t)B_OFF_B + (uint32_t)(kk * 136 + 8 * c) * 2, src);
            }
        }
        asm volatile("cp.async.commit_group;" ::: "memory");
    };

    auto comp = [&](int st) {
        const __half* As_ = pool + st * STAGE_H;
        const __half* Bs_ = pool + st * STAGE_H + 5120;
        #pragma unroll
        for (int kb = 0; kb < BK; kb += 16) {
            wmma::fragment<wmma::matrix_a, 16, 16, 16, __half, wmma::row_major> af[4];
            #pragma unroll
            for (int mb = 0; mb < 4; mb++)
                wmma::load_matrix_sync(af[mb], As_ + (wm + mb * 16) * 40 + kb, 40);
            #pragma unroll
            for (int nb = 0; nb < 2; nb++) {
                if (TRANSB) {
                    wmma::fragment<wmma::matrix_b, 16, 16, 16, __half, wmma::col_major> bf;
                    wmma::load_matrix_sync(bf, Bs_ + (wn + nb * 16) * 40 + kb, 40);
                    #pragma unroll
                    for (int mb = 0; mb < 4; mb++)
                        wmma::mma_sync(acc[mb][nb], af[mb], bf, acc[mb][nb]);
                } else {
                    wmma::fragment<wmma::matrix_b, 16, 16, 16, __half, wmma::row_major> bf;
                    wmma::load_matrix_sync(bf, Bs_ + kb * 136 + wn + nb * 16, 136);
                    #pragma unroll
                    for (int mb = 0; mb < 4; mb++)
                        wmma::mma_sync(acc[mb][nb], af[mb], bf, acc[mb][nb]);
                }
            }
        }
    };

    const int nk = K / BK;
    load_stage(0);
    for (int kt = 0; kt < nk; kt++) {
        if (kt + 1 < nk) {
            load_stage(kt + 1);
            asm volatile("cp.async.wait_group 1;" ::: "memory");
        } else {
            asm volatile("cp.async.wait_group 0;" ::: "memory");
        }
        __syncthreads();
        comp(kt & 1);
        __syncthreads();
    }

    // Epilogue: stage 16x32 warp slabs through smem for explicit (row,col) math.
    float* scratch = (float*)pool + wid * 640;   // [16][40]
    const int r = lane >> 1, chalf = (lane & 1) * 16;

    #pragma unroll
    for (int mb = 0; mb < 4; mb++) {
        wmma::store_matrix_sync(scratch,      acc[mb][0], 40, wmma::mem_row_major);
        wmma::store_matrix_sync(scratch + 16, acc[mb][1], 40, wmma::mem_row_major);
        __syncwarp();

        const int m = row0 + wm + mb * 16 + r;
        float inv = 1.0f;
        if (DIVROW) {
            float ls = 0.f;
            #pragma unroll
            for (int j = 0; j < 8; j++) ls += lpart[(long)z * 8192 + j * 1024 + m];
            inv = 1.0f / ls;
        }
        float rs = 0.f;
        #pragma unroll
        for (int it = 0; it < 4; it++) {
            int c = chalf + it * 4;
            float4 v = *(float4*)(scratch + r * 40 + c);
            int n = col0 + wn + c;
            v.x *= alpha; v.y *= alpha; v.z *= alpha; v.w *= alpha;
            if (ACT == 1 || ACT == 2) {
                v.x += bias[n];     v.y += bias[n + 1];
                v.z += bias[n + 2]; v.w += bias[n + 3];
            }
            if (ACT == 2) {
                v.x = v.x > 0.f ? v.x : expm1f(v.x);
                v.y = v.y > 0.f ? v.y : expm1f(v.y);
                v.z = v.z > 0.f ? v.z : expm1f(v.z);
                v.w = v.w > 0.f ? v.w : expm1f(v.w);
            }
            if (ACT == 3) {
                v.x = __expf(v.x); v.y = __expf(v.y);
                v.z = __expf(v.z); v.w = __expf(v.w);
                rs += v.x + v.y + v.z + v.w;
            }
            if (DIVROW) { v.x *= inv; v.y *= inv; v.z *= inv; v.w *= inv; }
            if (OUTH) {
                __half* Ch = (__half*)Cv + (long)z * sC;
                H2U2 pk;
                pk.h[0] = __floats2half2_rn(v.x, v.y);
                pk.h[1] = __floats2half2_rn(v.z, v.w);
                *(uint2*)&Ch[(long)m * ldc + n] = pk.u;
            } else {
                float* Cf = (float*)Cv + (long)z * sC;
                *(float4*)&Cf[(long)m * ldc + n] = v;
            }
        }
        if (ACT == 3) {
            rs += __shfl_xor_sync(0xffffffffu, rs, 1);
            if ((lane & 1) == 0) sm_l[wid >> 1][wm + mb * 16 + r] = rs;
        }
        __syncwarp();
    }

    if (ACT == 3) {
        __syncthreads();
        if (tid < 128) {
            float s = sm_l[0][tid] + sm_l[1][tid] + sm_l[2][tid] + sm_l[3][tid];
            lpart[(long)z * 8192 + blockIdx.x * 1024 + row0 + tid] = s;
        }
    }
}

// ---------------- fp32 -> fp16, 4 regions in one launch ----------------
__global__ __launch_bounds__(256)
void cvt4(const float* __restrict__ s0, __half* __restrict__ d0, int n0,
          const float* __restrict__ s1, __half* __restrict__ d1, int n1,
          const float* __restrict__ s2, __half* __restrict__ d2, int n2,
          const float* __restrict__ s3, __half* __restrict__ d3, int n3)
{
    int i = blockIdx.x * 256 + threadIdx.x;
    const float* s; __half* d;
    if (i < n0) { s = s0; d = d0; }
    else if ((i -= n0) < n1) { s = s1; d = d1; }
    else if ((i -= n1) < n2) { s = s2; d = d2; }
    else if ((i -= n2) < n3) { s = s3; d = d3; }
    else return;
    float4 v = ((const float4*)s)[i];
    H2U2 pk;
    pk.h[0] = __floats2half2_rn(v.x, v.y);
    pk.h[1] = __floats2half2_rn(v.z, v.w);
    ((uint2*)d)[i] = pk.u;
}

// ---------------- Pack Wq|Wk|Wv -> fp16 [H][512][640] ----------------
__global__ __launch_bounds__(256)
void pack_wqkv(const float* __restrict__ Wq, const float* __restrict__ Wk,
               const float* __restrict__ Wv, __half* __restrict__ W)
{
    int idx = blockIdx.x * 256 + threadIdx.x;   // over H*512*640
    int col = idx % 640;
    int hd  = idx / 640;                        // h*512 + d
    float v;
    if (col < 64)       v = Wq[(long)hd * 64 + col];
    else if (col < 128) v = Wk[(long)hd * 64 + (col - 64)];
    else                v = Wv[(long)hd * 512 + (col - 128)];
    W[idx] = __float2half(v);
}

// ---------------- Fused residual + LayerNorm, 512 cols (+optional fp16 copy) ----------------
__global__ __launch_bounds__(256)
void residual_ln(const float* __restrict__ X, const float* __restrict__ Y,
                 const float* __restrict__ g, const float* __restrict__ be,
                 float* __restrict__ out, __half* __restrict__ outh)
{
    const int NC = Dd;
    long row = blockIdx.x;
    const float* x = X + row * NC;
    const float* y = Y + row * NC;
    float* o = out + row * NC;
    int tid = threadIdx.x;
    __shared__ float red[256];

    float v0 = x[tid] + y[tid];
    float v1 = x[tid + 256] + y[tid + 256];

    red[tid] = v0 + v1; __syncthreads();
    for (int s = 128; s > 0; s >>= 1) {
        if (tid < s) red[tid] += red[tid + s];
        __syncthreads();
    }
    float mu = red[0] * (1.f / NC); __syncthreads();

    float d0 = v0 - mu, d1 = v1 - mu;
    red[tid] = d0 * d0 + d1 * d1; __syncthreads();
    for (int s = 128; s > 0; s >>= 1) {
        if (tid < s) red[tid] += red[tid + s];
        __syncthreads();
    }
    float rstd = rsqrtf(red[0] * (1.f / NC) + 1e-5f);

    float r0 = d0 * rstd * g[tid]       + be[tid];
    float r1 = d1 * rstd * g[tid + 256] + be[tid + 256];
    o[tid] = r0;
    o[tid + 256] = r1;
    if (outh) {
        outh[row * NC + tid]       = __float2half(r0);
        outh[row * NC + tid + 256] = __float2half(r1);
    }
}

// ---------------- Launch ----------------
extern "C" void kernel_launch(void* const* d_in, const int* in_sizes, int n_in,
                              void* d_out, int out_size)
{
    const float* x  = (const float*)d_in[0];
    const float* Wq = (const float*)d_in[1];
    const float* Wk = (const float*)d_in[2];
    const float* Wv = (const float*)d_in[3];
    const float* Wo = (const float*)d_in[4];
    const float* W1 = (const float*)d_in[5];
    const float* b1 = (const float*)d_in[6];
    const float* W2 = (const float*)d_in[7];
    const float* b2 = (const float*)d_in[8];
    const float* g1 = (const float*)d_in[9];
    const float* be1= (const float*)d_in[10];
    const float* g2 = (const float*)d_in[11];
    const float* be2= (const float*)d_in[12];
    float* out = (float*)d_out;

    __half *xh, *Wqkvh, *Woh, *W1h, *W2h, *QKV, *P, *O, *x1h, *h1;
    float *lp, *attn, *x1, *f;
    cudaGetSymbolAddress((void**)&xh,    g_xh);
    cudaGetSymbolAddress((void**)&Wqkvh, g_Wqkvh);
    cudaGetSymbolAddress((void**)&Woh,   g_Woh);
    cudaGetSymbolAddress((void**)&W1h,   g_W1h);
    cudaGetSymbolAddress((void**)&W2h,   g_W2h);
    cudaGetSymbolAddress((void**)&QKV,   g_QKV);
    cudaGetSymbolAddress((void**)&P,     g_P);
    cudaGetSymbolAddress((void**)&lp,    g_lpart);
    cudaGetSymbolAddress((void**)&O,     g_O);
    cudaGetSymbolAddress((void**)&attn,  g_attn);
    cudaGetSymbolAddress((void**)&x1,    g_x1);
    cudaGetSymbolAddress((void**)&x1h,   g_x1h);
    cudaGetSymbolAddress((void**)&h1,    g_h1);
    cudaGetSymbolAddress((void**)&f,     g_f);

    // 0. conversions / packs (2 launches)
    const int n_x = BS*Dd/4, n_wo = DH*Dd/4, n_w = Dd*Dd/4;
    cvt4<<<(n_x + n_wo + 2*n_w + 255)/256, 256>>>(
        x, xh, n_x, Wo, Woh, n_wo, W1, W1h, n_w, W2, W2h, n_w);
    pack_wqkv<<<(Hh*Dd*640)/256, 256>>>(Wq, Wk, Wv, Wqkvh);

    // 1. QKV[h] = x @ Wqkv[h]   [4096,512]x[512,640] per head, fp16 out
    tgemm<false,0,false,false,true><<<dim3(5, 32, Hh), 256>>>(
        xh, Wqkvh, QKV, nullptr, nullptr, BS, 640, Dd, Dd, 640, 640, 1.f,
        0L, (long)Dd*640, (long)BS*640);
    // 2. P = exp(Q @ K^T / 8), row partials -> lpart   per z=(h,b), fp16 out
    tgemm<true,3,false,false,true><<<dim3(8, 8, Hh*Bb), 256>>>(
        QKV, QKV + 64, P, nullptr, lp, Ss, Ss, Ee, 640, 640, Ss, 0.125f,
        (long)Ss*640, (long)Ss*640, (long)Ss*Ss);
    // 3. O = (P @ V) / rowsum   per z: [1024,1024]x[1024,512], fp16 out
    tgemm<false,0,false,true,true><<<dim3(4, 8, Hh*Bb), 256>>>(
        P, QKV + 128, O, nullptr, lp, Ss, Dd, Ss, Ss, 640, Dd, 1.f,
        (long)Ss*Ss, (long)Ss*640, (long)Ss*Dd);
    // 4. attn = a @ Wo with k=(h,d) permutation folded into the loads, fp32 out
    tgemm<false,0,true,false,false><<<dim3(4, 32, 1), 256>>>(
        O, Woh, attn, nullptr, nullptr, BS, Dd, DH, Dd, Dd, Dd, 1.f, 0L, 0L, 0L);
    // 5. x1 = LN(x + attn)  (fp32 + fp16 copy)
    residual_ln<<<BS, 256>>>(x, attn, g1, be1, x1, x1h);
    // 6. h1 = ELU(x1 @ W1 + b1), fp16 out
    tgemm<false,2,false,false,true><<<dim3(4, 32, 1), 256>>>(
        x1h, W1h, h1, b1, nullptr, BS, Dd, Dd, Dd, Dd, Dd, 1.f, 0L, 0L, 0L);
    // 7. f = h1 @ W2 + b2, fp32 out
    tgemm<false,1,false,false,false><<<dim3(4, 32, 1), 256>>>(
        h1, W2h, f, b2, nullptr, BS, Dd, Dd, Dd, Dd, Dd, 1.f, 0L, 0L, 0L);
    // 8. out = LN(x1 + f)
    residual_ln<<<BS, 256>>>(x1, f, g2, be2, out, nullptr);
}